// round 4
// baseline (speedup 1.0000x reference)
#include <cuda_runtime.h>
#include <cuda_bf16.h>

#define BATCH 16384
#define FEAT 512
#define NCLS 100000
#define ALPHA 0.5f
#define LAMDA 0.003f

// Scratch: per-class sample counts (allocation-free __device__ global).
__device__ int g_counts[NCLS];

__global__ void zero_counts_kernel() {
    int i = blockIdx.x * blockDim.x + threadIdx.x;
    if (i < NCLS) g_counts[i] = 0;
}

__global__ void count_kernel(const int* __restrict__ targets) {
    int i = blockIdx.x * blockDim.x + threadIdx.x;
    if (i < BATCH) atomicAdd(&g_counts[targets[i]], 1);
}

// Vectorized copy: centers -> new_centers region of d_out.
// NCLS*FEAT/4 = 12,800,000 float4 elements. Already at ~6.8 TB/s.
__global__ __launch_bounds__(256) void copy_centers_kernel(
    const float4* __restrict__ src, float4* __restrict__ dst) {
    int i = blockIdx.x * blockDim.x + threadIdx.x;
    if (i < (NCLS * FEAT / 4)) dst[i] = src[i];
}

// 256 threads = 4 rows x 64 threads. Each thread handles 2 float4s of its
// row (lane and lane+64), giving 4 big independent LDGs in flight per
// thread plus one broadcast target load per 2-warp group — enough MLP to
// saturate DRAM instead of exposing the targets->centers latency chain.
__global__ __launch_bounds__(256) void fused_main_kernel(
    const float4* __restrict__ inputs,
    const float4* __restrict__ centers,
    const float*  __restrict__ wpc,
    const int*    __restrict__ targets,
    float4* __restrict__ loss_out,
    float4* __restrict__ tw_out,
    float*  __restrict__ new_centers) {

    const int group = threadIdx.x >> 6;         // 0..3 : row within block
    const int lane  = threadIdx.x & 63;         // 0..63
    const int b = blockIdx.x * 4 + group;

    const int t = __ldg(&targets[b]);
    const float w = LAMDA * __ldg(&wpc[t]);
    const float s = ALPHA / (1.0f + (float)g_counts[t]);

    const size_t rb = (size_t)b * (FEAT / 4);
    const size_t rc = (size_t)t * (FEAT / 4);

    // 4 independent global loads issued back-to-back (MLP=4).
    const float4 x0 = inputs[rb + lane];
    const float4 x1 = inputs[rb + lane + 64];
    const float4 c0 = centers[rc + lane];
    const float4 c1 = centers[rc + lane + 64];

    float4 l0, l1;
    float dx;
    dx = x0.x - c0.x; l0.x = 0.5f * dx * dx;
    dx = x0.y - c0.y; l0.y = 0.5f * dx * dx;
    dx = x0.z - c0.z; l0.z = 0.5f * dx * dx;
    dx = x0.w - c0.w; l0.w = 0.5f * dx * dx;
    dx = x1.x - c1.x; l1.x = 0.5f * dx * dx;
    dx = x1.y - c1.y; l1.y = 0.5f * dx * dx;
    dx = x1.z - c1.z; l1.z = 0.5f * dx * dx;
    dx = x1.w - c1.w; l1.w = 0.5f * dx * dx;

    loss_out[rb + lane]      = l0;
    loss_out[rb + lane + 64] = l1;
    const float4 wv = make_float4(w, w, w, w);
    tw_out[rb + lane]      = wv;
    tw_out[rb + lane + 64] = wv;

    // Scatter-subtract ALPHA * x / (1 + count) into new_centers[t].
    // ~1.3k expected class collisions over 16384 samples -> near
    // conflict-free RED.F32 (no return value used, so ptxas emits RED).
    float* dst0 = new_centers + (size_t)t * FEAT + lane * 4;
    atomicAdd(dst0 + 0, -s * x0.x);
    atomicAdd(dst0 + 1, -s * x0.y);
    atomicAdd(dst0 + 2, -s * x0.z);
    atomicAdd(dst0 + 3, -s * x0.w);
    float* dst1 = dst0 + 256;
    atomicAdd(dst1 + 0, -s * x1.x);
    atomicAdd(dst1 + 1, -s * x1.y);
    atomicAdd(dst1 + 2, -s * x1.z);
    atomicAdd(dst1 + 3, -s * x1.w);
}

extern "C" void kernel_launch(void* const* d_in, const int* in_sizes, int n_in,
                              void* d_out, int out_size) {
    const float* inputs  = (const float*)d_in[0];   // [BATCH, FEAT]
    const float* centers = (const float*)d_in[1];   // [NCLS, FEAT]
    const float* wpc     = (const float*)d_in[2];   // [NCLS]
    const int*   targets = (const int*)d_in[3];     // [BATCH]

    float* out  = (float*)d_out;
    float* loss = out;                                  // [BATCH, FEAT]
    float* tw   = out + (size_t)BATCH * FEAT;           // [BATCH, FEAT]
    float* newc = out + (size_t)2 * BATCH * FEAT;       // [NCLS, FEAT]

    zero_counts_kernel<<<(NCLS + 255) / 256, 256>>>();
    count_kernel<<<(BATCH + 255) / 256, 256>>>(targets);
    copy_centers_kernel<<<(NCLS * FEAT / 4 + 255) / 256, 256>>>(
        (const float4*)centers, (float4*)newc);
    fused_main_kernel<<<BATCH / 4, 256>>>(
        (const float4*)inputs, (const float4*)centers, wpc, targets,
        (float4*)loss, (float4*)tw, newc);
}

// round 5
// speedup vs baseline: 1.1070x; 1.1070x over previous
#include <cuda_runtime.h>
#include <cuda_bf16.h>

#define BATCH 16384
#define FEAT 512
#define NCLS 100000
#define ALPHA 0.5f
#define LAMDA 0.003f

// Scratch: per-class sample counts (allocation-free __device__ global).
__device__ int g_counts[NCLS];

__global__ void zero_counts_kernel() {
    int i = blockIdx.x * blockDim.x + threadIdx.x;
    if (i < NCLS) g_counts[i] = 0;
}

__global__ void count_kernel(const int* __restrict__ targets) {
    int i = blockIdx.x * blockDim.x + threadIdx.x;
    if (i < BATCH) atomicAdd(&g_counts[targets[i]], 1);
}

// One 128-thread block per class row. Rows hit by exactly one sample are
// fully rewritten by fused_main_kernel, so skip them here (saves ~60 MB of
// DRAM traffic). Rows with cnt==0 or cnt>1 are copied (cnt>1 rows serve as
// the accumulation base for the duplicate-class atomic path).
__global__ __launch_bounds__(128) void copy_centers_kernel(
    const float4* __restrict__ src, float4* __restrict__ dst) {
    const int row = blockIdx.x;
    if (g_counts[row] == 1) return;          // fused kernel owns this row
    const size_t i = (size_t)row * (FEAT / 4) + threadIdx.x;
    dst[i] = src[i];
}

// One block per batch row. 128 threads x float4 = 512 feats.
// Computes loss + target_weights; for unique classes (cnt==1, ~98.4% of
// samples) writes the updated center row directly from registers — no
// atomics. Duplicate classes fall back to RED.F32 onto the copied base.
__global__ __launch_bounds__(128) void fused_main_kernel(
    const float4* __restrict__ inputs,
    const float4* __restrict__ centers,
    const float*  __restrict__ wpc,
    const int*    __restrict__ targets,
    float4* __restrict__ loss_out,
    float4* __restrict__ tw_out,
    float4* __restrict__ new_centers) {

    const int b  = blockIdx.x;
    const int d4 = threadIdx.x;               // 0..127

    const int t   = __ldg(&targets[b]);
    const int cnt = g_counts[t];
    const float w = LAMDA * __ldg(&wpc[t]);
    const float s = ALPHA / (1.0f + (float)cnt);

    const size_t ib = (size_t)b * (FEAT / 4) + d4;
    const size_t ic = (size_t)t * (FEAT / 4) + d4;
    const float4 x = inputs[ib];
    const float4 c = centers[ic];

    float4 l;
    float dx;
    dx = x.x - c.x; l.x = 0.5f * dx * dx;
    dx = x.y - c.y; l.y = 0.5f * dx * dx;
    dx = x.z - c.z; l.z = 0.5f * dx * dx;
    dx = x.w - c.w; l.w = 0.5f * dx * dx;

    loss_out[ib] = l;
    tw_out[ib]   = make_float4(w, w, w, w);

    if (cnt == 1) {
        // Sole sample of this class: new row = c - s*x, straight STG.128.
        new_centers[ic] = make_float4(c.x - s * x.x, c.y - s * x.y,
                                      c.z - s * x.z, c.w - s * x.w);
    } else {
        // Rare duplicate class (~1.6% of samples): accumulate onto the
        // copied base row with RED.F32.
        float* dst = (float*)&new_centers[ic];
        atomicAdd(dst + 0, -s * x.x);
        atomicAdd(dst + 1, -s * x.y);
        atomicAdd(dst + 2, -s * x.z);
        atomicAdd(dst + 3, -s * x.w);
    }
}

extern "C" void kernel_launch(void* const* d_in, const int* in_sizes, int n_in,
                              void* d_out, int out_size) {
    const float* inputs  = (const float*)d_in[0];   // [BATCH, FEAT]
    const float* centers = (const float*)d_in[1];   // [NCLS, FEAT]
    const float* wpc     = (const float*)d_in[2];   // [NCLS]
    const int*   targets = (const int*)d_in[3];     // [BATCH]

    float* out  = (float*)d_out;
    float* loss = out;                                  // [BATCH, FEAT]
    float* tw   = out + (size_t)BATCH * FEAT;           // [BATCH, FEAT]
    float* newc = out + (size_t)2 * BATCH * FEAT;       // [NCLS, FEAT]

    zero_counts_kernel<<<(NCLS + 255) / 256, 256>>>();
    count_kernel<<<(BATCH + 255) / 256, 256>>>(targets);
    copy_centers_kernel<<<NCLS, 128>>>(
        (const float4*)centers, (float4*)newc);
    fused_main_kernel<<<BATCH, 128>>>(
        (const float4*)inputs, (const float4*)centers, wpc, targets,
        (float4*)loss, (float4*)tw, (float4*)newc);
}

// round 6
// speedup vs baseline: 1.1804x; 1.0663x over previous
#include <cuda_runtime.h>
#include <cuda_bf16.h>

#define BATCH 16384
#define FEAT 512
#define NCLS 100000
#define ALPHA 0.5f
#define LAMDA 0.003f

// Scratch: per-class sample counts (allocation-free __device__ global).
__device__ int g_counts[NCLS];

__global__ void zero_counts_kernel() {
    int i = blockIdx.x * blockDim.x + threadIdx.x;
    if (i < NCLS) g_counts[i] = 0;
}

__global__ void count_kernel(const int* __restrict__ targets) {
    int i = blockIdx.x * blockDim.x + threadIdx.x;
    if (i < BATCH) atomicAdd(&g_counts[targets[i]], 1);
}

// Flat copy, 64B (4 consecutive float4) per thread so each thread touches
// exactly one class row: one count check, MLP=4, full coalescing.
// Rows with cnt==1 are fully rewritten by fused_main_kernel and skipped.
// Total threads: NCLS*FEAT/4/4 = 3,200,000.
__global__ __launch_bounds__(256) void copy_centers_kernel(
    const float4* __restrict__ src, float4* __restrict__ dst) {
    const int t = blockIdx.x * blockDim.x + threadIdx.x;   // 64B-chunk index
    const size_t i = (size_t)t * 4;                        // float4 index
    const int row = (int)(i >> 7);                         // 128 float4 per row
    if (row >= NCLS) return;
    if (g_counts[row] == 1) return;          // fused kernel owns this row
    float4 v0 = __ldcs(&src[i + 0]);
    float4 v1 = __ldcs(&src[i + 1]);
    float4 v2 = __ldcs(&src[i + 2]);
    float4 v3 = __ldcs(&src[i + 3]);
    __stcs(&dst[i + 0], v0);
    __stcs(&dst[i + 1], v1);
    __stcs(&dst[i + 2], v2);
    __stcs(&dst[i + 3], v3);
}

// One block per batch row. 128 threads x float4 = 512 feats.
// Computes loss + target_weights; for unique classes (cnt==1, ~98.4% of
// samples) writes the updated center row directly from registers — no
// atomics. Duplicate classes fall back to RED.F32 onto the copied base.
// All bulk traffic is write-once / read-once -> streaming (.cs) hints.
__global__ __launch_bounds__(128) void fused_main_kernel(
    const float4* __restrict__ inputs,
    const float4* __restrict__ centers,
    const float*  __restrict__ wpc,
    const int*    __restrict__ targets,
    float4* __restrict__ loss_out,
    float4* __restrict__ tw_out,
    float4* __restrict__ new_centers) {

    const int b  = blockIdx.x;
    const int d4 = threadIdx.x;               // 0..127

    const int t   = __ldg(&targets[b]);
    const int cnt = g_counts[t];
    const float w = LAMDA * __ldg(&wpc[t]);
    const float s = ALPHA / (1.0f + (float)cnt);

    const size_t ib = (size_t)b * (FEAT / 4) + d4;
    const size_t ic = (size_t)t * (FEAT / 4) + d4;
    const float4 x = __ldcs(&inputs[ib]);
    const float4 c = __ldcs(&centers[ic]);

    float4 l;
    float dx;
    dx = x.x - c.x; l.x = 0.5f * dx * dx;
    dx = x.y - c.y; l.y = 0.5f * dx * dx;
    dx = x.z - c.z; l.z = 0.5f * dx * dx;
    dx = x.w - c.w; l.w = 0.5f * dx * dx;

    __stcs(&loss_out[ib], l);
    __stcs(&tw_out[ib], make_float4(w, w, w, w));

    if (cnt == 1) {
        // Sole sample of this class: new row = c - s*x, straight STG.128.
        __stcs(&new_centers[ic],
               make_float4(c.x - s * x.x, c.y - s * x.y,
                           c.z - s * x.z, c.w - s * x.w));
    } else {
        // Rare duplicate class (~1.6% of samples): accumulate onto the
        // copied base row with RED.F32.
        float* dst = (float*)&new_centers[ic];
        atomicAdd(dst + 0, -s * x.x);
        atomicAdd(dst + 1, -s * x.y);
        atomicAdd(dst + 2, -s * x.z);
        atomicAdd(dst + 3, -s * x.w);
    }
}

extern "C" void kernel_launch(void* const* d_in, const int* in_sizes, int n_in,
                              void* d_out, int out_size) {
    const float* inputs  = (const float*)d_in[0];   // [BATCH, FEAT]
    const float* centers = (const float*)d_in[1];   // [NCLS, FEAT]
    const float* wpc     = (const float*)d_in[2];   // [NCLS]
    const int*   targets = (const int*)d_in[3];     // [BATCH]

    float* out  = (float*)d_out;
    float* loss = out;                                  // [BATCH, FEAT]
    float* tw   = out + (size_t)BATCH * FEAT;           // [BATCH, FEAT]
    float* newc = out + (size_t)2 * BATCH * FEAT;       // [NCLS, FEAT]

    zero_counts_kernel<<<(NCLS + 255) / 256, 256>>>();
    count_kernel<<<(BATCH + 255) / 256, 256>>>(targets);

    // 3.2M 64B-chunks -> 12500 blocks of 256 threads.
    const int chunks = NCLS * (FEAT / 4) / 4;
    copy_centers_kernel<<<(chunks + 255) / 256, 256>>>(
        (const float4*)centers, (float4*)newc);

    fused_main_kernel<<<BATCH, 128>>>(
        (const float4*)inputs, (const float4*)centers, wpc, targets,
        (float4*)loss, (float4*)tw, (float4*)newc);
}